// round 3
// baseline (speedup 1.0000x reference)
#include <cuda_runtime.h>
#include <math_constants.h>

// Problem shape (fixed by the benchmark)
#define BB   16
#define KC   5
#define NP   4096
#define DD   1024
#define KNN  9

#define BLOCKS_PER_B 32        // sims kernel: blocks per batch
#define RPG          4         // rows per warp group in sims kernel

// -------- scratch (no device allocation allowed -> __device__ globals) ------
__device__ float g_sims[BB * KC * NP];      // scaled cosine sims (1.3 MB)
__device__ float g_invnorm[BB * NP];        // 1/||patch||        (256 KB)

// -------- packed f32x2 FMA (Blackwell FFMA2; PTX-only, halves FFMA issue) ---
__device__ __forceinline__ void fma2(unsigned long long& d,
                                     unsigned long long a,
                                     unsigned long long b) {
    asm("fma.rn.f32x2 %0, %1, %2, %0;" : "+l"(d) : "l"(a), "l"(b));
}
__device__ __forceinline__ float sum2(unsigned long long p) {
    return __uint_as_float((unsigned int)(p & 0xffffffffu)) +
           __uint_as_float((unsigned int)(p >> 32));
}

// ============================================================================
// Kernel 1: one pass over patches (268 MB streamed once -> memory bound).
// Cue used RAW: per-(b,k) cue norm is a positive row-scalar -> same top-9 set,
// and the output involves normalized patches only. Each warp: 4 rows; per row
// 5 cue dots + self-dot via packed f32x2 FMAs (compute ~21k cyc/SM < DRAM
// ~42k cyc/SM -> DRAM-bound).
// ============================================================================
__global__ void __launch_bounds__(256, 2) sims_kernel(const float* __restrict__ patches,
                                                      const float* __restrict__ cue) {
    const int b = blockIdx.y;

    __shared__ ulonglong2 s_cue[KC * DD / 4];   // 5 x 1024 floats = 20 KB (raw)
    {
        const ulonglong2* src = (const ulonglong2*)(cue + (size_t)b * KC * DD);
        for (int i = threadIdx.x; i < KC * DD / 4; i += 256) s_cue[i] = src[i];
    }
    __syncthreads();

    const int warp = threadIdx.x >> 5;
    const int lane = threadIdx.x & 31;
    const int rows_per_block = NP / BLOCKS_PER_B;          // 128
    const int row0 = blockIdx.x * rows_per_block;

    for (int g = warp * RPG; g < rows_per_block; g += 8 * RPG) {
        const int r = row0 + g;
        const ulonglong2* p =
            (const ulonglong2*)(patches + ((size_t)b * NP + r) * DD);

        unsigned long long acc[RPG][6];
        #pragma unroll
        for (int rr = 0; rr < RPG; rr++)
            #pragma unroll
            for (int i = 0; i < 6; i++) acc[rr][i] = 0ull;   // (0.f, 0.f)

        #pragma unroll
        for (int j = 0; j < 8; j++) {
            const int off = lane + j * 32;                   // 256 x 16B per row
            ulonglong2 v[RPG];
            #pragma unroll
            for (int rr = 0; rr < RPG; rr++) v[rr] = p[off + rr * (DD / 4)];

            #pragma unroll
            for (int rr = 0; rr < RPG; rr++) {
                fma2(acc[rr][5], v[rr].x, v[rr].x);
                fma2(acc[rr][5], v[rr].y, v[rr].y);
            }
            #pragma unroll
            for (int k = 0; k < KC; k++) {
                const ulonglong2 c = s_cue[k * (DD / 4) + off];
                #pragma unroll
                for (int rr = 0; rr < RPG; rr++) {
                    fma2(acc[rr][k], v[rr].x, c.x);
                    fma2(acc[rr][k], v[rr].y, c.y);
                }
            }
        }

        #pragma unroll
        for (int rr = 0; rr < RPG; rr++) {
            float s[6];
            #pragma unroll
            for (int i = 0; i < 6; i++) s[i] = sum2(acc[rr][i]);
            #pragma unroll
            for (int i = 0; i < 6; i++)
                #pragma unroll
                for (int o = 16; o; o >>= 1)
                    s[i] += __shfl_xor_sync(0xffffffffu, s[i], o);
            if (lane == 0) {
                const float inv = 1.0f / fmaxf(sqrtf(s[5]), 1e-12f);
                g_invnorm[(size_t)b * NP + r + rr] = inv;
                #pragma unroll
                for (int k = 0; k < KC; k++)
                    g_sims[((size_t)b * KC + k) * NP + r + rr] = s[k] * inv;
            }
        }
    }
}

// ============================================================================
// Kernel 2: per (b,k): top-9 then mean of the 9 normalized patch rows.
// Two-level argmax: 256 threads each own 16 contiguous sims and post a local
// max; warp 0 alone runs 9 iterations over the 256 candidates (no block
// barriers inside the loop). Lowest-index tie-break throughout.
// ============================================================================
__global__ void __launch_bounds__(256) topk_kernel(const float* __restrict__ patches,
                                                   float* __restrict__ out) {
    const int bk = blockIdx.x;          // 0..79
    const int b = bk / KC;
    const int tid = threadIdx.x;

    __shared__ float s_sims[NP];        // 16 KB
    __shared__ float s_cval[256];
    __shared__ int   s_cidx[256];
    __shared__ int   s_top[KNN];
    __shared__ float s_inv[KNN];

    // Each thread owns elements [tid*16, tid*16+16). Load to regs + smem.
    float4 vv[4];
    {
        const float4* src = (const float4*)(g_sims + (size_t)bk * NP);
        float4* dst = (float4*)s_sims;
        const int base = tid * 4;       // in float4 units
        #pragma unroll
        for (int i = 0; i < 4; i++) { vv[i] = src[base + i]; dst[base + i] = vv[i]; }
    }
    // Local max (strict > on ascending scan keeps the lowest index on ties).
    {
        float bv = -CUDART_INF_F; int bi = tid * 16;
        const float* e = (const float*)vv;
        #pragma unroll
        for (int i = 0; i < 16; i++)
            if (e[i] > bv) { bv = e[i]; bi = tid * 16 + i; }
        s_cval[tid] = bv; s_cidx[tid] = bi;
    }
    __syncthreads();

    if (tid < 32) {
        const int lane = tid;
        for (int it = 0; it < KNN; it++) {
            float bv = -CUDART_INF_F; int bi = NP;
            #pragma unroll
            for (int j = 0; j < 8; j++) {
                const int t = lane * 8 + j;
                const float v = s_cval[t];
                const int   x = s_cidx[t];
                if (v > bv || (v == bv && x < bi)) { bv = v; bi = x; }
            }
            #pragma unroll
            for (int o = 16; o; o >>= 1) {
                const float ov = __shfl_xor_sync(0xffffffffu, bv, o);
                const int   oi = __shfl_xor_sync(0xffffffffu, bi, o);
                if (ov > bv || (ov == bv && oi < bi)) { bv = ov; bi = oi; }
            }
            if (lane == 0) {
                s_top[it] = bi;
                s_sims[bi] = -CUDART_INF_F;
                const int tw = bi >> 4;          // owning thread's segment
                float nv = -CUDART_INF_F; int ni = tw * 16;
                #pragma unroll
                for (int e2 = 0; e2 < 16; e2++) {
                    const float v = s_sims[tw * 16 + e2];
                    if (v > nv) { nv = v; ni = tw * 16 + e2; }
                }
                s_cval[tw] = nv; s_cidx[tw] = ni;
            }
            __syncwarp();
        }
    }
    __syncthreads();

    if (tid < KNN)
        s_inv[tid] = g_invnorm[(size_t)b * NP + s_top[tid]];
    __syncthreads();

    // each thread owns one float4 of the D=1024 output
    float4 acc = make_float4(0.f, 0.f, 0.f, 0.f);
    #pragma unroll
    for (int i = 0; i < KNN; i++) {
        const float4* prow =
            (const float4*)(patches + ((size_t)b * NP + s_top[i]) * DD);
        const float4 v = prow[tid];
        const float inv = s_inv[i];
        acc.x += v.x * inv;
        acc.y += v.y * inv;
        acc.z += v.z * inv;
        acc.w += v.w * inv;
    }
    const float sc = 1.0f / (float)KNN;
    float4 o4 = make_float4(acc.x * sc, acc.y * sc, acc.z * sc, acc.w * sc);
    ((float4*)out)[(size_t)bk * (DD / 4) + tid] = o4;
}

// ============================================================================
extern "C" void kernel_launch(void* const* d_in, const int* in_sizes, int n_in,
                              void* d_out, int out_size) {
    const float* cue     = (const float*)d_in[0];
    const float* patches = (const float*)d_in[1];
    // defensive: identify by element count (cue = 81920, patches = 67108864)
    if (n_in >= 2 && in_sizes[0] > in_sizes[1]) {
        cue     = (const float*)d_in[1];
        patches = (const float*)d_in[0];
    }

    dim3 g1(BLOCKS_PER_B, BB);
    sims_kernel<<<g1, 256>>>(patches, cue);

    topk_kernel<<<BB * KC, 256>>>(patches, (float*)d_out);
}

// round 4
// speedup vs baseline: 1.7105x; 1.7105x over previous
#include <cuda_runtime.h>
#include <math_constants.h>

// Problem shape (fixed by the benchmark)
#define BB   16
#define KC   5
#define NP   4096
#define DD   1024
#define KNN  9

#define BLOCKS_PER_B 32        // sims kernel: blocks per batch
#define RPG          4         // rows per warp group in sims kernel

// -------- scratch (no device allocation allowed -> __device__ globals) ------
__device__ float g_sims[BB * KC * NP];      // scaled cosine sims (1.3 MB)
__device__ float g_invnorm[BB * NP];        // 1/||patch||        (256 KB)

// ============================================================================
// Kernel 1: one pass over patches (268 MB streamed once -> memory bound).
// Cue used RAW: per-(b,k) cue norm is a positive row-scalar -> same top-9 set,
// and the output involves normalized patches only. Each warp: 4 rows, scalar
// FFMA, float4 loads with depth-1 software pipelining (prefetch next chunk
// before computing current) to double LDG in flight per warp.
// ============================================================================
__global__ void __launch_bounds__(256) sims_kernel(const float* __restrict__ patches,
                                                   const float* __restrict__ cue) {
    const int b = blockIdx.y;

    __shared__ float4 s_cue[KC * DD / 4];   // 5 x 1024 floats = 20 KB (raw cue)
    {
        const float4* src = (const float4*)(cue + (size_t)b * KC * DD);
        for (int i = threadIdx.x; i < KC * DD / 4; i += 256) s_cue[i] = src[i];
    }
    __syncthreads();

    const int warp = threadIdx.x >> 5;
    const int lane = threadIdx.x & 31;
    const int rows_per_block = NP / BLOCKS_PER_B;          // 128
    const int row0 = blockIdx.x * rows_per_block;

    for (int g = warp * RPG; g < rows_per_block; g += 8 * RPG) {
        const int r = row0 + g;
        const float4* p =
            (const float4*)(patches + ((size_t)b * NP + r) * DD);

        float acc[RPG][6];
        #pragma unroll
        for (int rr = 0; rr < RPG; rr++)
            #pragma unroll
            for (int i = 0; i < 6; i++) acc[rr][i] = 0.f;

        // pipeline: preload chunk 0
        float4 v[RPG], vn[RPG];
        #pragma unroll
        for (int rr = 0; rr < RPG; rr++)
            v[rr] = __ldcs(&p[lane + rr * (DD / 4)]);

        #pragma unroll
        for (int j = 0; j < 8; j++) {
            // prefetch next chunk while current chunk computes
            if (j < 7) {
                const int offn = lane + (j + 1) * 32;
                #pragma unroll
                for (int rr = 0; rr < RPG; rr++)
                    vn[rr] = __ldcs(&p[offn + rr * (DD / 4)]);
            }

            const int off = lane + j * 32;                 // 256 float4 per row
            #pragma unroll
            for (int rr = 0; rr < RPG; rr++) {
                acc[rr][5] = fmaf(v[rr].x, v[rr].x, acc[rr][5]);
                acc[rr][5] = fmaf(v[rr].y, v[rr].y, acc[rr][5]);
                acc[rr][5] = fmaf(v[rr].z, v[rr].z, acc[rr][5]);
                acc[rr][5] = fmaf(v[rr].w, v[rr].w, acc[rr][5]);
            }
            #pragma unroll
            for (int k = 0; k < KC; k++) {
                const float4 c = s_cue[k * (DD / 4) + off];
                #pragma unroll
                for (int rr = 0; rr < RPG; rr++) {
                    acc[rr][k] = fmaf(v[rr].x, c.x, acc[rr][k]);
                    acc[rr][k] = fmaf(v[rr].y, c.y, acc[rr][k]);
                    acc[rr][k] = fmaf(v[rr].z, c.z, acc[rr][k]);
                    acc[rr][k] = fmaf(v[rr].w, c.w, acc[rr][k]);
                }
            }
            #pragma unroll
            for (int rr = 0; rr < RPG; rr++) v[rr] = vn[rr];
        }

        #pragma unroll
        for (int rr = 0; rr < RPG; rr++) {
            #pragma unroll
            for (int i = 0; i < 6; i++)
                #pragma unroll
                for (int o = 16; o; o >>= 1)
                    acc[rr][i] += __shfl_xor_sync(0xffffffffu, acc[rr][i], o);
            if (lane == 0) {
                const float inv = 1.0f / fmaxf(sqrtf(acc[rr][5]), 1e-12f);
                g_invnorm[(size_t)b * NP + r + rr] = inv;
                #pragma unroll
                for (int k = 0; k < KC; k++)
                    g_sims[((size_t)b * KC + k) * NP + r + rr] = acc[rr][k] * inv;
            }
        }
    }
}

// ============================================================================
// Kernel 2: per (b,k): top-9 then mean of the 9 normalized patch rows.
// Two-level argmax: 256 threads each own 16 contiguous sims and post a local
// max; warp 0 alone runs 9 iterations over the 256 candidates. Lowest-index
// tie-break throughout (matches jax.lax.top_k).
// ============================================================================
__global__ void __launch_bounds__(256) topk_kernel(const float* __restrict__ patches,
                                                   float* __restrict__ out) {
    const int bk = blockIdx.x;          // 0..79
    const int b = bk / KC;
    const int tid = threadIdx.x;

    __shared__ float s_sims[NP];        // 16 KB
    __shared__ float s_cval[256];
    __shared__ int   s_cidx[256];
    __shared__ int   s_top[KNN];
    __shared__ float s_inv[KNN];

    // Each thread owns elements [tid*16, tid*16+16). Load to regs + smem.
    float4 vv[4];
    {
        const float4* src = (const float4*)(g_sims + (size_t)bk * NP);
        float4* dst = (float4*)s_sims;
        const int base = tid * 4;       // in float4 units
        #pragma unroll
        for (int i = 0; i < 4; i++) { vv[i] = src[base + i]; dst[base + i] = vv[i]; }
    }
    // Local max (strict > on ascending scan keeps the lowest index on ties).
    {
        float bv = -CUDART_INF_F; int bi = tid * 16;
        const float* e = (const float*)vv;
        #pragma unroll
        for (int i = 0; i < 16; i++)
            if (e[i] > bv) { bv = e[i]; bi = tid * 16 + i; }
        s_cval[tid] = bv; s_cidx[tid] = bi;
    }
    __syncthreads();

    if (tid < 32) {
        const int lane = tid;
        for (int it = 0; it < KNN; it++) {
            float bv = -CUDART_INF_F; int bi = NP;
            #pragma unroll
            for (int j = 0; j < 8; j++) {
                const int t = lane * 8 + j;
                const float v = s_cval[t];
                const int   x = s_cidx[t];
                if (v > bv || (v == bv && x < bi)) { bv = v; bi = x; }
            }
            #pragma unroll
            for (int o = 16; o; o >>= 1) {
                const float ov = __shfl_xor_sync(0xffffffffu, bv, o);
                const int   oi = __shfl_xor_sync(0xffffffffu, bi, o);
                if (ov > bv || (ov == bv && oi < bi)) { bv = ov; bi = oi; }
            }
            if (lane == 0) {
                s_top[it] = bi;
                s_sims[bi] = -CUDART_INF_F;
                const int tw = bi >> 4;          // owning thread's segment
                float nv = -CUDART_INF_F; int ni = tw * 16;
                #pragma unroll
                for (int e2 = 0; e2 < 16; e2++) {
                    const float v = s_sims[tw * 16 + e2];
                    if (v > nv) { nv = v; ni = tw * 16 + e2; }
                }
                s_cval[tw] = nv; s_cidx[tw] = ni;
            }
            __syncwarp();
        }
    }
    __syncthreads();

    if (tid < KNN)
        s_inv[tid] = g_invnorm[(size_t)b * NP + s_top[tid]];
    __syncthreads();

    // each thread owns one float4 of the D=1024 output
    float4 acc = make_float4(0.f, 0.f, 0.f, 0.f);
    #pragma unroll
    for (int i = 0; i < KNN; i++) {
        const float4* prow =
            (const float4*)(patches + ((size_t)b * NP + s_top[i]) * DD);
        const float4 v = prow[tid];
        const float inv = s_inv[i];
        acc.x += v.x * inv;
        acc.y += v.y * inv;
        acc.z += v.z * inv;
        acc.w += v.w * inv;
    }
    const float sc = 1.0f / (float)KNN;
    float4 o4 = make_float4(acc.x * sc, acc.y * sc, acc.z * sc, acc.w * sc);
    ((float4*)out)[(size_t)bk * (DD / 4) + tid] = o4;
}

// ============================================================================
extern "C" void kernel_launch(void* const* d_in, const int* in_sizes, int n_in,
                              void* d_out, int out_size) {
    const float* cue     = (const float*)d_in[0];
    const float* patches = (const float*)d_in[1];
    // defensive: identify by element count (cue = 81920, patches = 67108864)
    if (n_in >= 2 && in_sizes[0] > in_sizes[1]) {
        cue     = (const float*)d_in[1];
        patches = (const float*)d_in[0];
    }

    dim3 g1(BLOCKS_PER_B, BB);
    sims_kernel<<<g1, 256>>>(patches, cue);

    topk_kernel<<<BB * KC, 256>>>(patches, (float*)d_out);
}

// round 5
// speedup vs baseline: 1.8571x; 1.0857x over previous
#include <cuda_runtime.h>
#include <math_constants.h>

// Problem shape (fixed by the benchmark)
#define BB   16
#define KC   5
#define NP   4096
#define DD   1024
#define KNN  9

#define BLK_X 18               // sims blocks per batch (18*16 = 288 total)
#define RPG   4                // rows per unit (per warp iteration)
#define WPB   (BLK_X * 8)      // warps per batch = 144
#define NU    (NP / RPG)       // units (4-row groups) per batch = 1024

// -------- scratch (no device allocation allowed -> __device__ globals) ------
__device__ float g_sims[BB * KC * NP];      // scaled cosine sims (1.3 MB)
__device__ float g_invnorm[BB * NP];        // 1/||patch||        (256 KB)

// ============================================================================
// Kernel 1: one pass over patches (268 MB streamed once -> memory bound).
// Cue used RAW: per-(b,k) cue norm is a positive row-scalar -> same top-9 set,
// and the output involves normalized patches only.
// Grid = (18,16) = 288 blocks -> <=2 blocks/SM: exactly one wave.
// Per-warp flat unit loop with cross-unit prefetch: at the last chunk of a
// unit we prefetch the NEXT unit's first chunk, so LDGs stay in flight
// through the reduction/store tail.
// ============================================================================
__global__ void __launch_bounds__(256) sims_kernel(const float* __restrict__ patches,
                                                   const float* __restrict__ cue) {
    const int b = blockIdx.y;

    __shared__ float4 s_cue[KC * DD / 4];   // 5 x 1024 floats = 20 KB (raw cue)
    {
        const float4* src = (const float4*)(cue + (size_t)b * KC * DD);
        for (int i = threadIdx.x; i < KC * DD / 4; i += 256) s_cue[i] = src[i];
    }
    __syncthreads();

    const int warp = threadIdx.x >> 5;
    const int lane = threadIdx.x & 31;
    const float4* pbase = (const float4*)(patches + (size_t)b * NP * DD);

    int u = blockIdx.x * 8 + warp;          // first unit for this warp
    if (u >= NU) return;

    const float4* p = pbase + (size_t)u * RPG * (DD / 4);
    float4 v[RPG], vn[RPG];
    #pragma unroll
    for (int rr = 0; rr < RPG; rr++)
        v[rr] = __ldcs(&p[lane + rr * (DD / 4)]);

    while (true) {
        const int un = u + WPB;
        const float4* pn = pbase + (size_t)un * RPG * (DD / 4);
        const bool has_next = (un < NU);

        float acc[RPG][6];
        #pragma unroll
        for (int rr = 0; rr < RPG; rr++)
            #pragma unroll
            for (int i = 0; i < 6; i++) acc[rr][i] = 0.f;

        #pragma unroll
        for (int j = 0; j < 8; j++) {
            // prefetch: next chunk of this unit, or first chunk of next unit
            if (j < 7) {
                const int offn = lane + (j + 1) * 32;
                #pragma unroll
                for (int rr = 0; rr < RPG; rr++)
                    vn[rr] = __ldcs(&p[offn + rr * (DD / 4)]);
            } else if (has_next) {
                #pragma unroll
                for (int rr = 0; rr < RPG; rr++)
                    vn[rr] = __ldcs(&pn[lane + rr * (DD / 4)]);
            } else {
                #pragma unroll
                for (int rr = 0; rr < RPG; rr++) vn[rr] = v[rr];
            }

            const int off = lane + j * 32;                 // 256 float4 per row
            #pragma unroll
            for (int rr = 0; rr < RPG; rr++) {
                acc[rr][5] = fmaf(v[rr].x, v[rr].x, acc[rr][5]);
                acc[rr][5] = fmaf(v[rr].y, v[rr].y, acc[rr][5]);
                acc[rr][5] = fmaf(v[rr].z, v[rr].z, acc[rr][5]);
                acc[rr][5] = fmaf(v[rr].w, v[rr].w, acc[rr][5]);
            }
            #pragma unroll
            for (int k = 0; k < KC; k++) {
                const float4 c = s_cue[k * (DD / 4) + off];
                #pragma unroll
                for (int rr = 0; rr < RPG; rr++) {
                    acc[rr][k] = fmaf(v[rr].x, c.x, acc[rr][k]);
                    acc[rr][k] = fmaf(v[rr].y, c.y, acc[rr][k]);
                    acc[rr][k] = fmaf(v[rr].z, c.z, acc[rr][k]);
                    acc[rr][k] = fmaf(v[rr].w, c.w, acc[rr][k]);
                }
            }
            #pragma unroll
            for (int rr = 0; rr < RPG; rr++) v[rr] = vn[rr];
        }

        // Epilogue: butterfly leaves the sums in ALL lanes; lanes 0-4 store
        // the 5 sims, lane 5 stores invnorm (one predicated STG per row).
        const int rbase = u * RPG;
        #pragma unroll
        for (int rr = 0; rr < RPG; rr++) {
            #pragma unroll
            for (int i = 0; i < 6; i++)
                #pragma unroll
                for (int o = 16; o; o >>= 1)
                    acc[rr][i] += __shfl_xor_sync(0xffffffffu, acc[rr][i], o);
            const float inv = rsqrtf(fmaxf(acc[rr][5], 1e-24f));
            float val = acc[rr][0];
            if (lane == 1) val = acc[rr][1];
            if (lane == 2) val = acc[rr][2];
            if (lane == 3) val = acc[rr][3];
            if (lane == 4) val = acc[rr][4];
            if (lane < 5)
                g_sims[((size_t)b * KC + lane) * NP + rbase + rr] = val * inv;
            else if (lane == 5)
                g_invnorm[(size_t)b * NP + rbase + rr] = inv;
        }

        if (!has_next) break;
        u = un; p = pn;
    }
}

// ============================================================================
// Kernel 2: per (b,k): top-9 then mean of the 9 normalized patch rows.
// Two-level argmax: 256 threads each own 16 contiguous sims and post a local
// max; warp 0 alone runs 9 iterations over the 256 candidates. Lowest-index
// tie-break throughout (matches jax.lax.top_k).
// ============================================================================
__global__ void __launch_bounds__(256) topk_kernel(const float* __restrict__ patches,
                                                   float* __restrict__ out) {
    const int bk = blockIdx.x;          // 0..79
    const int b = bk / KC;
    const int tid = threadIdx.x;

    __shared__ float s_sims[NP];        // 16 KB
    __shared__ float s_cval[256];
    __shared__ int   s_cidx[256];
    __shared__ int   s_top[KNN];
    __shared__ float s_inv[KNN];

    // Each thread owns elements [tid*16, tid*16+16). Load to regs + smem.
    float4 vv[4];
    {
        const float4* src = (const float4*)(g_sims + (size_t)bk * NP);
        float4* dst = (float4*)s_sims;
        const int base = tid * 4;       // in float4 units
        #pragma unroll
        for (int i = 0; i < 4; i++) { vv[i] = src[base + i]; dst[base + i] = vv[i]; }
    }
    // Local max (strict > on ascending scan keeps the lowest index on ties).
    {
        float bv = -CUDART_INF_F; int bi = tid * 16;
        const float* e = (const float*)vv;
        #pragma unroll
        for (int i = 0; i < 16; i++)
            if (e[i] > bv) { bv = e[i]; bi = tid * 16 + i; }
        s_cval[tid] = bv; s_cidx[tid] = bi;
    }
    __syncthreads();

    if (tid < 32) {
        const int lane = tid;
        for (int it = 0; it < KNN; it++) {
            float bv = -CUDART_INF_F; int bi = NP;
            #pragma unroll
            for (int j = 0; j < 8; j++) {
                const int t = lane * 8 + j;
                const float v = s_cval[t];
                const int   x = s_cidx[t];
                if (v > bv || (v == bv && x < bi)) { bv = v; bi = x; }
            }
            #pragma unroll
            for (int o = 16; o; o >>= 1) {
                const float ov = __shfl_xor_sync(0xffffffffu, bv, o);
                const int   oi = __shfl_xor_sync(0xffffffffu, bi, o);
                if (ov > bv || (ov == bv && oi < bi)) { bv = ov; bi = oi; }
            }
            if (lane == 0) {
                s_top[it] = bi;
                s_sims[bi] = -CUDART_INF_F;
                const int tw = bi >> 4;          // owning thread's segment
                float nv = -CUDART_INF_F; int ni = tw * 16;
                #pragma unroll
                for (int e2 = 0; e2 < 16; e2++) {
                    const float v = s_sims[tw * 16 + e2];
                    if (v > nv) { nv = v; ni = tw * 16 + e2; }
                }
                s_cval[tw] = nv; s_cidx[tw] = ni;
            }
            __syncwarp();
        }
    }
    __syncthreads();

    if (tid < KNN)
        s_inv[tid] = g_invnorm[(size_t)b * NP + s_top[tid]];
    __syncthreads();

    // each thread owns one float4 of the D=1024 output
    float4 acc = make_float4(0.f, 0.f, 0.f, 0.f);
    #pragma unroll
    for (int i = 0; i < KNN; i++) {
        const float4* prow =
            (const float4*)(patches + ((size_t)b * NP + s_top[i]) * DD);
        const float4 v = prow[tid];
        const float inv = s_inv[i];
        acc.x += v.x * inv;
        acc.y += v.y * inv;
        acc.z += v.z * inv;
        acc.w += v.w * inv;
    }
    const float sc = 1.0f / (float)KNN;
    float4 o4 = make_float4(acc.x * sc, acc.y * sc, acc.z * sc, acc.w * sc);
    ((float4*)out)[(size_t)bk * (DD / 4) + tid] = o4;
}

// ============================================================================
extern "C" void kernel_launch(void* const* d_in, const int* in_sizes, int n_in,
                              void* d_out, int out_size) {
    const float* cue     = (const float*)d_in[0];
    const float* patches = (const float*)d_in[1];
    // defensive: identify by element count (cue = 81920, patches = 67108864)
    if (n_in >= 2 && in_sizes[0] > in_sizes[1]) {
        cue     = (const float*)d_in[1];
        patches = (const float*)d_in[0];
    }

    dim3 g1(BLK_X, BB);
    sims_kernel<<<g1, 256>>>(patches, cue);

    topk_kernel<<<BB * KC, 256>>>(patches, (float*)d_out);
}

// round 6
// speedup vs baseline: 2.0968x; 1.1290x over previous
#include <cuda_runtime.h>
#include <math_constants.h>

// Problem shape (fixed by the benchmark)
#define BB   16
#define KC   5
#define NP   4096
#define DD   1024
#define KNN  9

#define BLK_X 32               // sims blocks per batch (32*16 = 512 total, one wave @4/SM)
#define RPG   2                // rows per unit (low regs -> 4 blocks/SM)
#define WPB   (BLK_X * 8)      // warps per batch = 256
#define NU    (NP / RPG)       // units per batch = 2048 (8 units/warp)

// -------- scratch (no device allocation allowed -> __device__ globals) ------
__device__ float g_sims[BB * KC * NP];      // scaled cosine sims (1.3 MB)
__device__ float g_invnorm[BB * NP];        // 1/||patch||        (256 KB)

// ============================================================================
// Kernel 1: one pass over patches (268 MB streamed once -> memory bound).
// Cue used RAW: per-(b,k) cue norm is a positive row-scalar -> same top-9 set,
// and the output involves normalized patches only.
// RPG=2 + depth-2 prefetch ring + launch_bounds(256,4): 32 warps/SM, two
// 512B-chunks in flight per warp at all times (incl. across unit boundaries).
// ============================================================================
__global__ void __launch_bounds__(256, 4) sims_kernel(const float* __restrict__ patches,
                                                      const float* __restrict__ cue) {
    const int b = blockIdx.y;

    __shared__ float4 s_cue[KC * DD / 4];   // 5 x 1024 floats = 20 KB (raw cue)
    {
        const float4* src = (const float4*)(cue + (size_t)b * KC * DD);
        for (int i = threadIdx.x; i < KC * DD / 4; i += 256) s_cue[i] = src[i];
    }
    __syncthreads();

    const int warp = threadIdx.x >> 5;
    const int lane = threadIdx.x & 31;
    const float4* pbase = (const float4*)(patches + (size_t)b * NP * DD);

    int u = blockIdx.x * 8 + warp;          // first unit for this warp
    const float4* p = pbase + (size_t)u * RPG * (DD / 4);

    // depth-2 ring: v0 = current chunk, v1 = next, v2 = prefetch target
    float4 v0[RPG], v1[RPG], v2[RPG];
    #pragma unroll
    for (int rr = 0; rr < RPG; rr++) {
        v0[rr] = __ldcs(&p[lane + rr * (DD / 4)]);
        v1[rr] = __ldcs(&p[lane + 32 + rr * (DD / 4)]);
    }

    while (true) {
        const int un = u + WPB;
        const bool has_next = (un < NU);
        const float4* pn = pbase + (size_t)un * RPG * (DD / 4);

        float acc[RPG][6];
        #pragma unroll
        for (int rr = 0; rr < RPG; rr++)
            #pragma unroll
            for (int i = 0; i < 6; i++) acc[rr][i] = 0.f;

        #pragma unroll
        for (int j = 0; j < 8; j++) {
            // prefetch chunk j+2 (this unit) or chunk j-6 (next unit)
            if (j < 6) {
                const int offn = lane + (j + 2) * 32;
                #pragma unroll
                for (int rr = 0; rr < RPG; rr++)
                    v2[rr] = __ldcs(&p[offn + rr * (DD / 4)]);
            } else if (has_next) {
                const int offn = lane + (j - 6) * 32;
                #pragma unroll
                for (int rr = 0; rr < RPG; rr++)
                    v2[rr] = __ldcs(&pn[offn + rr * (DD / 4)]);
            }

            const int off = lane + j * 32;                 // 256 float4 per row
            #pragma unroll
            for (int rr = 0; rr < RPG; rr++) {
                acc[rr][5] = fmaf(v0[rr].x, v0[rr].x, acc[rr][5]);
                acc[rr][5] = fmaf(v0[rr].y, v0[rr].y, acc[rr][5]);
                acc[rr][5] = fmaf(v0[rr].z, v0[rr].z, acc[rr][5]);
                acc[rr][5] = fmaf(v0[rr].w, v0[rr].w, acc[rr][5]);
            }
            #pragma unroll
            for (int k = 0; k < KC; k++) {
                const float4 c = s_cue[k * (DD / 4) + off];
                #pragma unroll
                for (int rr = 0; rr < RPG; rr++) {
                    acc[rr][k] = fmaf(v0[rr].x, c.x, acc[rr][k]);
                    acc[rr][k] = fmaf(v0[rr].y, c.y, acc[rr][k]);
                    acc[rr][k] = fmaf(v0[rr].z, c.z, acc[rr][k]);
                    acc[rr][k] = fmaf(v0[rr].w, c.w, acc[rr][k]);
                }
            }
            // rotate ring (renamed away by ptxas under full unroll)
            #pragma unroll
            for (int rr = 0; rr < RPG; rr++) { v0[rr] = v1[rr]; v1[rr] = v2[rr]; }
        }

        // Epilogue: butterfly leaves sums in ALL lanes; lanes 0-4 store the 5
        // sims, lane 5 stores invnorm (one predicated STG per row).
        const int rbase = u * RPG;
        #pragma unroll
        for (int rr = 0; rr < RPG; rr++) {
            #pragma unroll
            for (int i = 0; i < 6; i++)
                #pragma unroll
                for (int o = 16; o; o >>= 1)
                    acc[rr][i] += __shfl_xor_sync(0xffffffffu, acc[rr][i], o);
            const float inv = rsqrtf(fmaxf(acc[rr][5], 1e-24f));
            float val = acc[rr][0];
            if (lane == 1) val = acc[rr][1];
            if (lane == 2) val = acc[rr][2];
            if (lane == 3) val = acc[rr][3];
            if (lane == 4) val = acc[rr][4];
            if (lane < 5)
                g_sims[((size_t)b * KC + lane) * NP + rbase + rr] = val * inv;
            else if (lane == 5)
                g_invnorm[(size_t)b * NP + rbase + rr] = inv;
        }

        if (!has_next) break;
        u = un; p = pn;
    }
}

// ============================================================================
// Kernel 2: per (b,k): top-9 then mean of the 9 normalized patch rows.
// Two-level argmax; warp 0 runs 9 iterations; the owner-segment rescan is
// done by 16 lanes in parallel + 4-stage shfl reduce. Lowest-index tie-break
// throughout (matches jax.lax.top_k).
// ============================================================================
__global__ void __launch_bounds__(256) topk_kernel(const float* __restrict__ patches,
                                                   float* __restrict__ out) {
    const int bk = blockIdx.x;          // 0..79
    const int b = bk / KC;
    const int tid = threadIdx.x;

    __shared__ float s_sims[NP];        // 16 KB
    __shared__ float s_cval[256];
    __shared__ int   s_cidx[256];
    __shared__ int   s_top[KNN];
    __shared__ float s_inv[KNN];

    // Each thread owns elements [tid*16, tid*16+16). Load to regs + smem.
    float4 vv[4];
    {
        const float4* src = (const float4*)(g_sims + (size_t)bk * NP);
        float4* dst = (float4*)s_sims;
        const int base = tid * 4;       // in float4 units
        #pragma unroll
        for (int i = 0; i < 4; i++) { vv[i] = src[base + i]; dst[base + i] = vv[i]; }
    }
    // Local max (strict > on ascending scan keeps the lowest index on ties).
    {
        float bv = -CUDART_INF_F; int bi = tid * 16;
        const float* e = (const float*)vv;
        #pragma unroll
        for (int i = 0; i < 16; i++)
            if (e[i] > bv) { bv = e[i]; bi = tid * 16 + i; }
        s_cval[tid] = bv; s_cidx[tid] = bi;
    }
    __syncthreads();

    if (tid < 32) {
        const int lane = tid;
        for (int it = 0; it < KNN; it++) {
            float bv = -CUDART_INF_F; int bi = NP;
            #pragma unroll
            for (int j = 0; j < 8; j++) {
                const int t = lane * 8 + j;
                const float v = s_cval[t];
                const int   x = s_cidx[t];
                if (v > bv || (v == bv && x < bi)) { bv = v; bi = x; }
            }
            #pragma unroll
            for (int o = 16; o; o >>= 1) {
                const float ov = __shfl_xor_sync(0xffffffffu, bv, o);
                const int   oi = __shfl_xor_sync(0xffffffffu, bi, o);
                if (ov > bv || (ov == bv && oi < bi)) { bv = ov; bi = oi; }
            }
            // all lanes now hold the global (bv, bi)
            if (lane == 0) { s_top[it] = bi; s_sims[bi] = -CUDART_INF_F; }
            __syncwarp();
            // parallel rescan of the owning 16-element segment
            const int tw = bi >> 4;
            float nv = -CUDART_INF_F; int ni = NP;
            if (lane < 16) { nv = s_sims[tw * 16 + lane]; ni = tw * 16 + lane; }
            #pragma unroll
            for (int o = 8; o; o >>= 1) {
                const float ov = __shfl_xor_sync(0xffffffffu, nv, o);
                const int   oi = __shfl_xor_sync(0xffffffffu, ni, o);
                if (ov > nv || (ov == nv && oi < ni)) { nv = ov; ni = oi; }
            }
            if (lane == 0) { s_cval[tw] = nv; s_cidx[tw] = ni; }
            __syncwarp();
        }
    }
    __syncthreads();

    if (tid < KNN)
        s_inv[tid] = g_invnorm[(size_t)b * NP + s_top[tid]];
    __syncthreads();

    // each thread owns one float4 of the D=1024 output
    float4 acc = make_float4(0.f, 0.f, 0.f, 0.f);
    #pragma unroll
    for (int i = 0; i < KNN; i++) {
        const float4* prow =
            (const float4*)(patches + ((size_t)b * NP + s_top[i]) * DD);
        const float4 v = prow[tid];
        const float inv = s_inv[i];
        acc.x += v.x * inv;
        acc.y += v.y * inv;
        acc.z += v.z * inv;
        acc.w += v.w * inv;
    }
    const float sc = 1.0f / (float)KNN;
    float4 o4 = make_float4(acc.x * sc, acc.y * sc, acc.z * sc, acc.w * sc);
    ((float4*)out)[(size_t)bk * (DD / 4) + tid] = o4;
}

// ============================================================================
extern "C" void kernel_launch(void* const* d_in, const int* in_sizes, int n_in,
                              void* d_out, int out_size) {
    const float* cue     = (const float*)d_in[0];
    const float* patches = (const float*)d_in[1];
    // defensive: identify by element count (cue = 81920, patches = 67108864)
    if (n_in >= 2 && in_sizes[0] > in_sizes[1]) {
        cue     = (const float*)d_in[1];
        patches = (const float*)d_in[0];
    }

    dim3 g1(BLK_X, BB);
    sims_kernel<<<g1, 256>>>(patches, cue);

    topk_kernel<<<BB * KC, 256>>>(patches, (float*)d_out);
}

// round 7
// speedup vs baseline: 2.1667x; 1.0333x over previous
#include <cuda_runtime.h>
#include <math_constants.h>

// Problem shape (fixed by the benchmark)
#define BB   16
#define KC   5
#define NP   4096
#define DD   1024
#define KNN  9

#define BLK_X 32               // sims blocks per batch (32*16 = 512, one wave @4/SM)
#define RPG   2                // rows per unit
#define UPW   8                // units per warp (8 warps * 8 units * 2 rows = 128 rows/block)
#define ROWS_PER_BLK 128
#define NCAND (BLK_X * KNN)    // 288 candidates per (b,k)

// -------- scratch (no device allocation allowed -> __device__ globals) ------
__device__ float2 g_cand[BB * KC * NCAND];  // (val, idx-as-float-bits) 184 KB
__device__ float  g_invnorm[BB * NP];       // 1/||patch||             256 KB

// ============================================================================
// Kernel 1: one pass over patches (268 MB streamed once -> memory bound) PLUS
// first-level top-9. Cue used RAW (positive row-scalar -> same top-9 set; the
// output only involves normalized patches). Block bx covers contiguous rows
// [bx*128, bx*128+128): cosines staged in smem, then warps 0-4 select the
// block-local top-9 per cue and emit (val,idx) candidates. Exact: global
// top-9 is contained in the union of partition top-9s; ties resolved
// (val desc, idx asc) at every level.
// ============================================================================
__global__ void __launch_bounds__(256, 4) sims_kernel(const float* __restrict__ patches,
                                                      const float* __restrict__ cue) {
    const int b = blockIdx.y;
    const int bx = blockIdx.x;

    __shared__ float4 s_cue[KC * DD / 4];        // 20 KB (raw cue)
    __shared__ float  s_s[KC][ROWS_PER_BLK];     // 2.5 KB block-local cosines
    {
        const float4* src = (const float4*)(cue + (size_t)b * KC * DD);
        for (int i = threadIdx.x; i < KC * DD / 4; i += 256) s_cue[i] = src[i];
    }
    __syncthreads();

    const int warp = threadIdx.x >> 5;
    const int lane = threadIdx.x & 31;
    const float4* pbase = (const float4*)(patches + (size_t)b * NP * DD);
    const int u0 = bx * (ROWS_PER_BLK / RPG);    // first unit of this block

    // warp handles local units warp + m*8, m = 0..7 (depth-2 prefetch ring)
    const float4* p = pbase + (size_t)(u0 + warp) * RPG * (DD / 4);
    float4 v0[RPG], v1[RPG], v2[RPG];
    #pragma unroll
    for (int rr = 0; rr < RPG; rr++) {
        v0[rr] = __ldcs(&p[lane + rr * (DD / 4)]);
        v1[rr] = __ldcs(&p[lane + 32 + rr * (DD / 4)]);
    }

    for (int m = 0; m < UPW; m++) {
        const bool has_next = (m < UPW - 1);
        const float4* pn = p + 8 * RPG * (DD / 4);    // next unit (stride 8)

        float acc[RPG][6];
        #pragma unroll
        for (int rr = 0; rr < RPG; rr++)
            #pragma unroll
            for (int i = 0; i < 6; i++) acc[rr][i] = 0.f;

        #pragma unroll
        for (int j = 0; j < 8; j++) {
            if (j < 6) {
                const int offn = lane + (j + 2) * 32;
                #pragma unroll
                for (int rr = 0; rr < RPG; rr++)
                    v2[rr] = __ldcs(&p[offn + rr * (DD / 4)]);
            } else if (has_next) {
                const int offn = lane + (j - 6) * 32;
                #pragma unroll
                for (int rr = 0; rr < RPG; rr++)
                    v2[rr] = __ldcs(&pn[offn + rr * (DD / 4)]);
            }

            const int off = lane + j * 32;
            #pragma unroll
            for (int rr = 0; rr < RPG; rr++) {
                acc[rr][5] = fmaf(v0[rr].x, v0[rr].x, acc[rr][5]);
                acc[rr][5] = fmaf(v0[rr].y, v0[rr].y, acc[rr][5]);
                acc[rr][5] = fmaf(v0[rr].z, v0[rr].z, acc[rr][5]);
                acc[rr][5] = fmaf(v0[rr].w, v0[rr].w, acc[rr][5]);
            }
            #pragma unroll
            for (int k = 0; k < KC; k++) {
                const float4 c = s_cue[k * (DD / 4) + off];
                #pragma unroll
                for (int rr = 0; rr < RPG; rr++) {
                    acc[rr][k] = fmaf(v0[rr].x, c.x, acc[rr][k]);
                    acc[rr][k] = fmaf(v0[rr].y, c.y, acc[rr][k]);
                    acc[rr][k] = fmaf(v0[rr].z, c.z, acc[rr][k]);
                    acc[rr][k] = fmaf(v0[rr].w, c.w, acc[rr][k]);
                }
            }
            #pragma unroll
            for (int rr = 0; rr < RPG; rr++) { v0[rr] = v1[rr]; v1[rr] = v2[rr]; }
        }

        // epilogue: butterfly -> all lanes hold sums; stage cosines in smem
        const int lrow0 = (warp + m * 8) * RPG;          // local row base 0..127
        #pragma unroll
        for (int rr = 0; rr < RPG; rr++) {
            #pragma unroll
            for (int i = 0; i < 6; i++)
                #pragma unroll
                for (int o = 16; o; o >>= 1)
                    acc[rr][i] += __shfl_xor_sync(0xffffffffu, acc[rr][i], o);
            const float inv = rsqrtf(fmaxf(acc[rr][5], 1e-24f));
            float val = acc[rr][0];
            if (lane == 1) val = acc[rr][1];
            if (lane == 2) val = acc[rr][2];
            if (lane == 3) val = acc[rr][3];
            if (lane == 4) val = acc[rr][4];
            if (lane < 5)
                s_s[lane][lrow0 + rr] = val * inv;
            else if (lane == 5)
                g_invnorm[(size_t)b * NP + bx * ROWS_PER_BLK + lrow0 + rr] = inv;
        }

        if (has_next) p = pn;
    }
    __syncthreads();

    // Block-local top-9 per cue: warp k selects from s_s[k][0..128).
    if (warp < KC) {
        const int k = warp;
        float v[4];
        const int base = lane * 4;
        #pragma unroll
        for (int i = 0; i < 4; i++) v[i] = s_s[k][base + i];

        float2* cand = g_cand + ((size_t)(b * KC + k) * BLK_X + bx) * KNN;
        for (int it = 0; it < KNN; it++) {
            float bv = -CUDART_INF_F; int bi = ROWS_PER_BLK;
            #pragma unroll
            for (int i = 0; i < 4; i++)
                if (v[i] > bv) { bv = v[i]; bi = base + i; }   // lowest idx on tie
            #pragma unroll
            for (int o = 16; o; o >>= 1) {
                const float ov = __shfl_xor_sync(0xffffffffu, bv, o);
                const int   oi = __shfl_xor_sync(0xffffffffu, bi, o);
                if (ov > bv || (ov == bv && oi < bi)) { bv = ov; bi = oi; }
            }
            if ((bi >> 2) == lane) v[bi & 3] = -CUDART_INF_F;  // mask winner
            if (lane == 0)
                cand[it] = make_float2(bv, __int_as_float(bx * ROWS_PER_BLK + bi));
        }
    }
}

// ============================================================================
// Kernel 2: merge 288 candidates per (b,k) -> global top-9, then mean of the
// 9 normalized patch rows. grid = 80 blocks, 256 threads.
// ============================================================================
__global__ void __launch_bounds__(256) topk_kernel(const float* __restrict__ patches,
                                                   float* __restrict__ out) {
    const int bk = blockIdx.x;          // 0..79
    const int b = bk / KC;
    const int tid = threadIdx.x;

    __shared__ float s_v[NCAND];
    __shared__ int   s_i[NCAND];
    __shared__ int   s_top[KNN];
    __shared__ float s_inv[KNN];

    const float2* cand = g_cand + (size_t)bk * NCAND;
    for (int t = tid; t < NCAND; t += 256) {
        const float2 c = cand[t];
        s_v[t] = c.x;
        s_i[t] = __float_as_int(c.y);
    }
    __syncthreads();

    if (tid < 32) {
        const int lane = tid;
        // lane holds slots lane + s*32, s = 0..8 (register resident)
        float v[9]; int x[9];
        #pragma unroll
        for (int s = 0; s < 9; s++) {
            const int g = lane + s * 32;
            v[s] = s_v[g]; x[s] = s_i[g];
        }
        for (int it = 0; it < KNN; it++) {
            float bv = -CUDART_INF_F; int bi = NP; int bs = 0;
            #pragma unroll
            for (int s = 0; s < 9; s++)
                if (v[s] > bv || (v[s] == bv && x[s] < bi)) { bv = v[s]; bi = x[s]; bs = s; }
            int blane = lane;
            #pragma unroll
            for (int o = 16; o; o >>= 1) {
                const float ov = __shfl_xor_sync(0xffffffffu, bv, o);
                const int   oi = __shfl_xor_sync(0xffffffffu, bi, o);
                const int   os = __shfl_xor_sync(0xffffffffu, bs, o);
                const int   ol = __shfl_xor_sync(0xffffffffu, blane, o);
                if (ov > bv || (ov == bv && oi < bi)) { bv = ov; bi = oi; bs = os; blane = ol; }
            }
            if (lane == blane) v[bs] = -CUDART_INF_F;          // mask winner
            if (lane == 0) s_top[it] = bi;
        }
    }
    __syncthreads();

    if (tid < KNN)
        s_inv[tid] = g_invnorm[(size_t)b * NP + s_top[tid]];
    __syncthreads();

    // each thread owns one float4 of the D=1024 output
    float4 acc = make_float4(0.f, 0.f, 0.f, 0.f);
    #pragma unroll
    for (int i = 0; i < KNN; i++) {
        const float4* prow =
            (const float4*)(patches + ((size_t)b * NP + s_top[i]) * DD);
        const float4 v = prow[tid];
        const float inv = s_inv[i];
        acc.x += v.x * inv;
        acc.y += v.y * inv;
        acc.z += v.z * inv;
        acc.w += v.w * inv;
    }
    const float sc = 1.0f / (float)KNN;
    float4 o4 = make_float4(acc.x * sc, acc.y * sc, acc.z * sc, acc.w * sc);
    ((float4*)out)[(size_t)bk * (DD / 4) + tid] = o4;
}

// ============================================================================
extern "C" void kernel_launch(void* const* d_in, const int* in_sizes, int n_in,
                              void* d_out, int out_size) {
    const float* cue     = (const float*)d_in[0];
    const float* patches = (const float*)d_in[1];
    // defensive: identify by element count (cue = 81920, patches = 67108864)
    if (n_in >= 2 && in_sizes[0] > in_sizes[1]) {
        cue     = (const float*)d_in[1];
        patches = (const float*)d_in[0];
    }

    dim3 g1(BLK_X, BB);
    sims_kernel<<<g1, 256>>>(patches, cue);

    topk_kernel<<<BB * KC, 256>>>(patches, (float*)d_out);
}